// round 6
// baseline (speedup 1.0000x reference)
#include <cuda_runtime.h>
#include <cuda_bf16.h>

// CostGenerator: cost[b,c,d,h,w] = (w>=d) ? left[b,c,h,w] - right[b,c,h,w-d] : 0
// B=2, C=32, H=128, W=256, D=48 (f32). HBM-write-bound: 403 MB out, 16 MB in.
//
// R5 change vs R4 (the 67.6us winner): wave-quantization fix. R4 launched
// 2048 CTAs at occupancy 8/SM (n_conc=1184) -> 2 waves, 2nd wave 73% full,
// matching the observed ~69% DRAM ceiling. R5 launches exactly 1024 CTAs,
// each doing exactly 2 row-groups (double-buffered smem staging) -> single
// fully-resident wave, uniform DRAM demand, balanced finish.
// Compute path identical to R4: grouped-by-4 disparities, 2x LDS.128 per
// group, shifted windows assembled from registers, plain STG.128 stores.

#define B_  2
#define C_  32
#define H_  128
#define W_  256
#define D_  48
#define PAD 48                  // left pad, multiple of 4, >= D
#define ROWS_PER_BLOCK 4
#define THREADS 256             // 64 float4-lanes per row * 4 rows
#define GROUPS (B_ * C_ * (H_ / ROWS_PER_BLOCK))   // 2048 row-groups
#define GRID   (GROUPS / 2)                         // 1024 CTAs, 2 groups each

__global__ __launch_bounds__(THREADS, 8)
void cost_generator_kernel(const float* __restrict__ left,
                           const float* __restrict__ right,
                           float* __restrict__ out)
{
    __shared__ float s_right[2][ROWS_PER_BLOCK][PAD + W_];

    const int tid = threadIdx.x;
    const int r   = tid >> 6;        // row within group: 0..3
    const int v   = tid & 63;        // float4 lane within row: 0..63
    const int w0  = v << 2;          // first w this thread owns (4-aligned)

    #pragma unroll
    for (int it = 0; it < 2; ++it) {
        const int wid = blockIdx.x + it * GRID;     // row-group id: 0..2047

        const int hb  = wid % (H_ / ROWS_PER_BLOCK);
        const int bc  = wid / (H_ / ROWS_PER_BLOCK);   // fused (b*C + c)
        const int h   = hb * ROWS_PER_BLOCK + r;

        const size_t in_off = ((size_t)bc * H_ + h) * W_;

        // Left values live in registers for the whole d-loop.
        const float4 l4 = *reinterpret_cast<const float4*>(left + in_off + w0);

        // Zero the pad and stage this row of right into this iteration's
        // smem buffer (double-buffered: no sync needed before writing).
        if (v < PAD / 4) {
            *reinterpret_cast<float4*>(&s_right[it][r][v << 2]) =
                make_float4(0.f, 0.f, 0.f, 0.f);
        }
        *reinterpret_cast<float4*>(&s_right[it][r][PAD + w0]) =
            *reinterpret_cast<const float4*>(right + in_off + w0);
        __syncthreads();

        const float* sr = &s_right[it][r][PAD];

        // Output base for d=0; each d advances by one H*W plane.
        float* op = out + (((size_t)bc * D_) * H_ + h) * W_ + w0;

        #pragma unroll
        for (int g = 0; g < D_ / 4; ++g) {
            const int i0 = w0 - 4 * g;   // 4-aligned shifted base

            // Two aligned vector loads cover all 4 shifted windows.
            const float4 Vhi = *reinterpret_cast<const float4*>(sr + i0);
            const float4 Vlo = *reinterpret_cast<const float4*>(sr + i0 - 4);

            float4 o;

            // d = 4g   : {Vhi.x, Vhi.y, Vhi.z, Vhi.w}
            o.x = (i0     >= 0) ? (l4.x - Vhi.x) : 0.f;
            o.y = (i0 + 1 >= 0) ? (l4.y - Vhi.y) : 0.f;
            o.z = (i0 + 2 >= 0) ? (l4.z - Vhi.z) : 0.f;
            o.w = (i0 + 3 >= 0) ? (l4.w - Vhi.w) : 0.f;
            *reinterpret_cast<float4*>(op) = o;
            op += (size_t)H_ * W_;

            // d = 4g+1 : {Vlo.w, Vhi.x, Vhi.y, Vhi.z}
            o.x = (i0     >= 1) ? (l4.x - Vlo.w) : 0.f;
            o.y = (i0 + 1 >= 1) ? (l4.y - Vhi.x) : 0.f;
            o.z = (i0 + 2 >= 1) ? (l4.z - Vhi.y) : 0.f;
            o.w = (i0 + 3 >= 1) ? (l4.w - Vhi.z) : 0.f;
            *reinterpret_cast<float4*>(op) = o;
            op += (size_t)H_ * W_;

            // d = 4g+2 : {Vlo.z, Vlo.w, Vhi.x, Vhi.y}
            o.x = (i0     >= 2) ? (l4.x - Vlo.z) : 0.f;
            o.y = (i0 + 1 >= 2) ? (l4.y - Vlo.w) : 0.f;
            o.z = (i0 + 2 >= 2) ? (l4.z - Vhi.x) : 0.f;
            o.w = (i0 + 3 >= 2) ? (l4.w - Vhi.y) : 0.f;
            *reinterpret_cast<float4*>(op) = o;
            op += (size_t)H_ * W_;

            // d = 4g+3 : {Vlo.y, Vlo.z, Vlo.w, Vhi.x}
            o.x = (i0     >= 3) ? (l4.x - Vlo.y) : 0.f;
            o.y = (i0 + 1 >= 3) ? (l4.y - Vlo.z) : 0.f;
            o.z = (i0 + 2 >= 3) ? (l4.z - Vlo.w) : 0.f;
            o.w = (i0 + 3 >= 3) ? (l4.w - Vhi.x) : 0.f;
            *reinterpret_cast<float4*>(op) = o;
            op += (size_t)H_ * W_;
        }
    }
}

extern "C" void kernel_launch(void* const* d_in, const int* in_sizes, int n_in,
                              void* d_out, int out_size)
{
    const float* left  = (const float*)d_in[0];
    const float* right = (const float*)d_in[1];
    float* out = (float*)d_out;

    cost_generator_kernel<<<GRID, THREADS>>>(left, right, out);
}

// round 10
// speedup vs baseline: 1.1493x; 1.1493x over previous
#include <cuda_runtime.h>
#include <cuda_bf16.h>

// CostGenerator: cost[b,c,d,h,w] = (w>=d) ? left[b,c,h,w] - right[b,c,h,w-d] : 0
// B=2, C=32, H=128, W=256, D=48 (f32). HBM-write-bound: 403 MB out, 16 MB in.
//
// R6 change vs R4 (67.6us best): granularity. R5 proved coarser CTAs hurt
// (1024 CTAs -> 78.6us: SM imbalance 6-vs-7 + long serial tail). R6 goes the
// other way: 128-thread CTAs (2 rows each), grid=4096, occupancy 16/SM ->
// same 64 resident warps/SM, but the end-of-kernel drain tail is half as
// long and the work-stealing scheduler gets 2x more pieces to balance.
// Compute path identical to R4: grouped-by-4 disparities, 2x LDS.128 per
// group, register-assembled shifted windows, plain STG.128.

#define B_  2
#define C_  32
#define H_  128
#define W_  256
#define D_  48
#define PAD 48                  // left pad, multiple of 4, >= D
#define ROWS_PER_BLOCK 2
#define THREADS 128             // 64 float4-lanes per row * 2 rows
#define GRID (B_ * C_ * (H_ / ROWS_PER_BLOCK))   // 4096 CTAs

__global__ __launch_bounds__(THREADS, 16)
void cost_generator_kernel(const float* __restrict__ left,
                           const float* __restrict__ right,
                           float* __restrict__ out)
{
    __shared__ float s_right[ROWS_PER_BLOCK][PAD + W_];

    const int tid = threadIdx.x;
    const int r   = tid >> 6;        // row within block: 0..1
    const int v   = tid & 63;        // float4 lane within row: 0..63
    const int w0  = v << 2;          // first w this thread owns (4-aligned)

    const int hb  = blockIdx.x % (H_ / ROWS_PER_BLOCK);
    const int bc  = blockIdx.x / (H_ / ROWS_PER_BLOCK);   // fused (b*C + c)
    const int h   = hb * ROWS_PER_BLOCK + r;

    const size_t in_off = ((size_t)bc * H_ + h) * W_;

    // Left values live in registers for the whole d-loop.
    const float4 l4 = *reinterpret_cast<const float4*>(left + in_off + w0);

    // Zero the pad and stage this row of right into smem (48x reuse).
    if (v < PAD / 4) {
        *reinterpret_cast<float4*>(&s_right[r][v << 2]) = make_float4(0.f, 0.f, 0.f, 0.f);
    }
    *reinterpret_cast<float4*>(&s_right[r][PAD + w0]) =
        *reinterpret_cast<const float4*>(right + in_off + w0);
    __syncthreads();

    const float* sr = &s_right[r][PAD];

    // Output base for d=0; each d advances by one H*W plane.
    float* op = out + (((size_t)bc * D_) * H_ + h) * W_ + w0;

    #pragma unroll
    for (int g = 0; g < D_ / 4; ++g) {
        const int i0 = w0 - 4 * g;   // 4-aligned shifted base for this group

        // Two aligned vector loads cover all 4 shifted windows of the group.
        const float4 Vhi = *reinterpret_cast<const float4*>(sr + i0);
        const float4 Vlo = *reinterpret_cast<const float4*>(sr + i0 - 4);

        float4 o;

        // d = 4g   : {Vhi.x, Vhi.y, Vhi.z, Vhi.w}
        o.x = (i0     >= 0) ? (l4.x - Vhi.x) : 0.f;
        o.y = (i0 + 1 >= 0) ? (l4.y - Vhi.y) : 0.f;
        o.z = (i0 + 2 >= 0) ? (l4.z - Vhi.z) : 0.f;
        o.w = (i0 + 3 >= 0) ? (l4.w - Vhi.w) : 0.f;
        *reinterpret_cast<float4*>(op) = o;
        op += (size_t)H_ * W_;

        // d = 4g+1 : {Vlo.w, Vhi.x, Vhi.y, Vhi.z}
        o.x = (i0     >= 1) ? (l4.x - Vlo.w) : 0.f;
        o.y = (i0 + 1 >= 1) ? (l4.y - Vhi.x) : 0.f;
        o.z = (i0 + 2 >= 1) ? (l4.z - Vhi.y) : 0.f;
        o.w = (i0 + 3 >= 1) ? (l4.w - Vhi.z) : 0.f;
        *reinterpret_cast<float4*>(op) = o;
        op += (size_t)H_ * W_;

        // d = 4g+2 : {Vlo.z, Vlo.w, Vhi.x, Vhi.y}
        o.x = (i0     >= 2) ? (l4.x - Vlo.z) : 0.f;
        o.y = (i0 + 1 >= 2) ? (l4.y - Vlo.w) : 0.f;
        o.z = (i0 + 2 >= 2) ? (l4.z - Vhi.x) : 0.f;
        o.w = (i0 + 3 >= 2) ? (l4.w - Vhi.y) : 0.f;
        *reinterpret_cast<float4*>(op) = o;
        op += (size_t)H_ * W_;

        // d = 4g+3 : {Vlo.y, Vlo.z, Vlo.w, Vhi.x}
        o.x = (i0     >= 3) ? (l4.x - Vlo.y) : 0.f;
        o.y = (i0 + 1 >= 3) ? (l4.y - Vlo.z) : 0.f;
        o.z = (i0 + 2 >= 3) ? (l4.z - Vlo.w) : 0.f;
        o.w = (i0 + 3 >= 3) ? (l4.w - Vhi.x) : 0.f;
        *reinterpret_cast<float4*>(op) = o;
        op += (size_t)H_ * W_;
    }
}

extern "C" void kernel_launch(void* const* d_in, const int* in_sizes, int n_in,
                              void* d_out, int out_size)
{
    const float* left  = (const float*)d_in[0];
    const float* right = (const float*)d_in[1];
    float* out = (float*)d_out;

    cost_generator_kernel<<<GRID, THREADS>>>(left, right, out);
}

// round 13
// speedup vs baseline: 1.1894x; 1.0349x over previous
#include <cuda_runtime.h>
#include <cuda_bf16.h>
#include <cstdint>

// CostGenerator: cost[b,c,d,h,w] = (w>=d) ? left[b,c,h,w] - right[b,c,h,w-d] : 0
// B=2, C=32, H=128, W=256, D=48 (f32). 403 MB out, 16 MB in.
//
// R12 = R10 resubmit (container infra flake, kernel never ran) with one
// improvement: staging reclaim uses cp.async.bulk.wait_group.READ (bulk
// engine has consumed the smem tile) instead of full write completion.
//
// Theory under test: all schedule variants plateau at DRAM~70% active with
// no pipe saturated -> warp-interleaved 512B stores hopping 128KB between
// d-planes starve DRAM of large bursts. Per (CTA,d) the output is one
// contiguous 4KB span: stage in smem, emit ONE cp.async.bulk per d,
// 4-deep pipelined. Compute path identical to R4 (67.6us best).

#define B_  2
#define C_  32
#define H_  128
#define W_  256
#define D_  48
#define PAD 48                  // left pad, multiple of 4, >= D
#define ROWS_PER_BLOCK 4
#define THREADS 256             // 64 float4-lanes per row * 4 rows
#define GRID (B_ * C_ * (H_ / ROWS_PER_BLOCK))   // 2048 CTAs
#define NSTAGE 4                // bulk-store pipeline depth
#define TILE_BYTES (ROWS_PER_BLOCK * W_ * 4)     // 4096 B per d

__device__ __forceinline__ uint32_t smem_u32(const void* p) {
    uint32_t a;
    asm("{ .reg .u64 t; cvta.to.shared.u64 t, %1; cvt.u32.u64 %0, t; }"
        : "=r"(a) : "l"(p));
    return a;
}

__global__ __launch_bounds__(THREADS, 8)
void cost_generator_kernel(const float* __restrict__ left,
                           const float* __restrict__ right,
                           float* __restrict__ out)
{
    __shared__ float s_right[ROWS_PER_BLOCK][PAD + W_];
    __shared__ __align__(16) float s_out[NSTAGE][ROWS_PER_BLOCK * W_]; // 4x4KB

    const int tid = threadIdx.x;
    const int r   = tid >> 6;        // row within block: 0..3
    const int v   = tid & 63;        // float4 lane within row: 0..63
    const int w0  = v << 2;          // first w this thread owns (4-aligned)

    const int hb  = blockIdx.x % (H_ / ROWS_PER_BLOCK);
    const int bc  = blockIdx.x / (H_ / ROWS_PER_BLOCK);   // fused (b*C + c)
    const int h   = hb * ROWS_PER_BLOCK + r;

    const size_t in_off = ((size_t)bc * H_ + h) * W_;

    // Left values live in registers for the whole d-loop.
    const float4 l4 = *reinterpret_cast<const float4*>(left + in_off + w0);

    // Zero the pad and stage this row of right into smem (48x reuse).
    if (v < PAD / 4) {
        *reinterpret_cast<float4*>(&s_right[r][v << 2]) = make_float4(0.f, 0.f, 0.f, 0.f);
    }
    *reinterpret_cast<float4*>(&s_right[r][PAD + w0]) =
        *reinterpret_cast<const float4*>(right + in_off + w0);
    __syncthreads();

    const float* sr = &s_right[r][PAD];

    // Destination: per d, rows h0..h0+3 of plane (bc,d) = contiguous 4KB.
    const size_t plane = (size_t)H_ * W_;
    float* obase = out + ((size_t)bc * D_) * plane
                       + (size_t)(hb * ROWS_PER_BLOCK) * W_;

    // Each thread's slot in the staging tile: exactly tid*16 bytes.
    uint32_t sb[NSTAGE];
    #pragma unroll
    for (int s = 0; s < NSTAGE; ++s) sb[s] = smem_u32(&s_out[s][0]);
    const uint32_t my_off = (uint32_t)tid * 16u;

    #pragma unroll
    for (int g = 0; g < D_ / 4; ++g) {
        const int i0 = w0 - 4 * g;   // 4-aligned shifted base for this group

        // Two aligned vector loads cover all 4 shifted windows of the group.
        const float4 Vhi = *reinterpret_cast<const float4*>(sr + i0);
        const float4 Vlo = *reinterpret_cast<const float4*>(sr + i0 - 4);

        #pragma unroll
        for (int j = 0; j < 4; ++j) {
            const int d = 4 * g + j;
            const int stage = d & (NSTAGE - 1);

            // Reclaim the staging buffer: need only the bulk engine to have
            // READ stage d-4's tile (not full write completion).
            if (d >= NSTAGE) {
                if (tid == 0)
                    asm volatile("cp.async.bulk.wait_group.read %0;"
                                 :: "n"(NSTAGE - 1) : "memory");
            }
            __syncthreads();

            float4 o;
            if (j == 0) {
                o.x = (i0     >= 0) ? (l4.x - Vhi.x) : 0.f;
                o.y = (i0 + 1 >= 0) ? (l4.y - Vhi.y) : 0.f;
                o.z = (i0 + 2 >= 0) ? (l4.z - Vhi.z) : 0.f;
                o.w = (i0 + 3 >= 0) ? (l4.w - Vhi.w) : 0.f;
            } else if (j == 1) {
                o.x = (i0     >= 1) ? (l4.x - Vlo.w) : 0.f;
                o.y = (i0 + 1 >= 1) ? (l4.y - Vhi.x) : 0.f;
                o.z = (i0 + 2 >= 1) ? (l4.z - Vhi.y) : 0.f;
                o.w = (i0 + 3 >= 1) ? (l4.w - Vhi.z) : 0.f;
            } else if (j == 2) {
                o.x = (i0     >= 2) ? (l4.x - Vlo.z) : 0.f;
                o.y = (i0 + 1 >= 2) ? (l4.y - Vlo.w) : 0.f;
                o.z = (i0 + 2 >= 2) ? (l4.z - Vhi.x) : 0.f;
                o.w = (i0 + 3 >= 2) ? (l4.w - Vhi.y) : 0.f;
            } else {
                o.x = (i0     >= 3) ? (l4.x - Vlo.y) : 0.f;
                o.y = (i0 + 1 >= 3) ? (l4.y - Vlo.z) : 0.f;
                o.z = (i0 + 2 >= 3) ? (l4.z - Vlo.w) : 0.f;
                o.w = (i0 + 3 >= 3) ? (l4.w - Vhi.x) : 0.f;
            }

            // Stage into smem (thread tid owns bytes [tid*16, tid*16+16)).
            asm volatile("st.shared.v4.b32 [%0], {%1, %2, %3, %4};"
                         :: "r"(sb[stage] + my_off),
                            "r"(__float_as_uint(o.x)), "r"(__float_as_uint(o.y)),
                            "r"(__float_as_uint(o.z)), "r"(__float_as_uint(o.w))
                         : "memory");
            // Order generic-proxy STS before async-proxy bulk read.
            asm volatile("fence.proxy.async.shared::cta;" ::: "memory");
            __syncthreads();

            // One thread emits the 4KB contiguous bulk store for this d.
            if (tid == 0) {
                asm volatile(
                    "cp.async.bulk.global.shared::cta.bulk_group [%0], [%1], %2;"
                    :: "l"(obase + (size_t)d * plane), "r"(sb[stage]),
                       "r"((uint32_t)TILE_BYTES)
                    : "memory");
                asm volatile("cp.async.bulk.commit_group;" ::: "memory");
            }
        }
    }

    // Drain all pending bulk stores before CTA exit.
    if (tid == 0)
        asm volatile("cp.async.bulk.wait_group %0;" :: "n"(0) : "memory");
}

extern "C" void kernel_launch(void* const* d_in, const int* in_sizes, int n_in,
                              void* d_out, int out_size)
{
    const float* left  = (const float*)d_in[0];
    const float* right = (const float*)d_in[1];
    float* out = (float*)d_out;

    cost_generator_kernel<<<GRID, THREADS>>>(left, right, out);
}

// round 15
// speedup vs baseline: 1.1900x; 1.0005x over previous
#include <cuda_runtime.h>
#include <cuda_bf16.h>
#include <cstdint>

// CostGenerator: cost[b,c,d,h,w] = (w>=d) ? left[b,c,h,w] - right[b,c,h,w-d] : 0
// B=2, C=32, H=128, W=256, D=48 (f32). 403 MB out, 16 MB in.
//
// R13 vs R12 (66.0us best): halve synchronization. R12 showed the bulk-store
// path wins via occupancy/issue (92%/24%), not DRAM% (stuck ~70% across all
// store paths -> path-independent ceiling). Remaining loop overhead is 2
// syncthreads + fence + wait PER d (96 barrier events). R13 pairs the
// d-iterations: compute d and d+1 into two stages, one fence+sync, one
// commit covering both 4KB bulks (group = 8KB). 48 barrier events, same
// 4-tile pipeline depth. Compute path identical.

#define B_  2
#define C_  32
#define H_  128
#define W_  256
#define D_  48
#define PAD 48                  // left pad, multiple of 4, >= D
#define ROWS_PER_BLOCK 4
#define THREADS 256             // 64 float4-lanes per row * 4 rows
#define GRID (B_ * C_ * (H_ / ROWS_PER_BLOCK))   // 2048 CTAs
#define NSTAGE 4                // staging tiles (2 pairs in flight)
#define TILE_BYTES (ROWS_PER_BLOCK * W_ * 4)     // 4096 B per d

__device__ __forceinline__ uint32_t smem_u32(const void* p) {
    uint32_t a;
    asm("{ .reg .u64 t; cvta.to.shared.u64 t, %1; cvt.u32.u64 %0, t; }"
        : "=r"(a) : "l"(p));
    return a;
}

__global__ __launch_bounds__(THREADS, 8)
void cost_generator_kernel(const float* __restrict__ left,
                           const float* __restrict__ right,
                           float* __restrict__ out)
{
    __shared__ float s_right[ROWS_PER_BLOCK][PAD + W_];
    __shared__ __align__(16) float s_out[NSTAGE][ROWS_PER_BLOCK * W_]; // 4x4KB

    const int tid = threadIdx.x;
    const int r   = tid >> 6;        // row within block: 0..3
    const int v   = tid & 63;        // float4 lane within row: 0..63
    const int w0  = v << 2;          // first w this thread owns (4-aligned)

    const int hb  = blockIdx.x % (H_ / ROWS_PER_BLOCK);
    const int bc  = blockIdx.x / (H_ / ROWS_PER_BLOCK);   // fused (b*C + c)
    const int h   = hb * ROWS_PER_BLOCK + r;

    const size_t in_off = ((size_t)bc * H_ + h) * W_;

    // Left values live in registers for the whole d-loop.
    const float4 l4 = *reinterpret_cast<const float4*>(left + in_off + w0);

    // Zero the pad and stage this row of right into smem (48x reuse).
    if (v < PAD / 4) {
        *reinterpret_cast<float4*>(&s_right[r][v << 2]) = make_float4(0.f, 0.f, 0.f, 0.f);
    }
    *reinterpret_cast<float4*>(&s_right[r][PAD + w0]) =
        *reinterpret_cast<const float4*>(right + in_off + w0);
    __syncthreads();

    const float* sr = &s_right[r][PAD];

    // Destination: per d, rows h0..h0+3 of plane (bc,d) = contiguous 4KB.
    const size_t plane = (size_t)H_ * W_;
    float* obase = out + ((size_t)bc * D_) * plane
                       + (size_t)(hb * ROWS_PER_BLOCK) * W_;

    uint32_t sb[NSTAGE];
    #pragma unroll
    for (int s = 0; s < NSTAGE; ++s) sb[s] = smem_u32(&s_out[s][0]);
    const uint32_t my_off = (uint32_t)tid * 16u;   // thread's 16B slot

    #pragma unroll
    for (int g = 0; g < D_ / 4; ++g) {
        const int i0 = w0 - 4 * g;   // 4-aligned shifted base for this group

        // Two aligned vector loads cover all 4 shifted windows of the group.
        const float4 Vhi = *reinterpret_cast<const float4*>(sr + i0);
        const float4 Vlo = *reinterpret_cast<const float4*>(sr + i0 - 4);

        #pragma unroll
        for (int p = 0; p < 2; ++p) {          // pair of disparities
            const int d0 = 4 * g + 2 * p;      // first d of this pair
            const int s0 = d0 & (NSTAGE - 1);  // stage for d0
            const int s1 = (d0 + 1) & (NSTAGE - 1);

            // Reclaim: stages {s0,s1} were used by pair d0-4. Allow 1
            // pending group (the previous pair) before reuse.
            if (d0 >= NSTAGE) {
                if (tid == 0)
                    asm volatile("cp.async.bulk.wait_group.read %0;"
                                 :: "n"(1) : "memory");
            }
            __syncthreads();

            // ---- disparity d0 (j = 2p) ----
            float4 o;
            if (p == 0) {   // j = 0 : {Vhi.x, Vhi.y, Vhi.z, Vhi.w}
                o.x = (i0     >= 0) ? (l4.x - Vhi.x) : 0.f;
                o.y = (i0 + 1 >= 0) ? (l4.y - Vhi.y) : 0.f;
                o.z = (i0 + 2 >= 0) ? (l4.z - Vhi.z) : 0.f;
                o.w = (i0 + 3 >= 0) ? (l4.w - Vhi.w) : 0.f;
            } else {        // j = 2 : {Vlo.z, Vlo.w, Vhi.x, Vhi.y}
                o.x = (i0     >= 2) ? (l4.x - Vlo.z) : 0.f;
                o.y = (i0 + 1 >= 2) ? (l4.y - Vlo.w) : 0.f;
                o.z = (i0 + 2 >= 2) ? (l4.z - Vhi.x) : 0.f;
                o.w = (i0 + 3 >= 2) ? (l4.w - Vhi.y) : 0.f;
            }
            asm volatile("st.shared.v4.b32 [%0], {%1, %2, %3, %4};"
                         :: "r"(sb[s0] + my_off),
                            "r"(__float_as_uint(o.x)), "r"(__float_as_uint(o.y)),
                            "r"(__float_as_uint(o.z)), "r"(__float_as_uint(o.w))
                         : "memory");

            // ---- disparity d0+1 (j = 2p+1) ----
            if (p == 0) {   // j = 1 : {Vlo.w, Vhi.x, Vhi.y, Vhi.z}
                o.x = (i0     >= 1) ? (l4.x - Vlo.w) : 0.f;
                o.y = (i0 + 1 >= 1) ? (l4.y - Vhi.x) : 0.f;
                o.z = (i0 + 2 >= 1) ? (l4.z - Vhi.y) : 0.f;
                o.w = (i0 + 3 >= 1) ? (l4.w - Vhi.z) : 0.f;
            } else {        // j = 3 : {Vlo.y, Vlo.z, Vlo.w, Vhi.x}
                o.x = (i0     >= 3) ? (l4.x - Vlo.y) : 0.f;
                o.y = (i0 + 1 >= 3) ? (l4.y - Vlo.z) : 0.f;
                o.z = (i0 + 2 >= 3) ? (l4.z - Vlo.w) : 0.f;
                o.w = (i0 + 3 >= 3) ? (l4.w - Vhi.x) : 0.f;
            }
            asm volatile("st.shared.v4.b32 [%0], {%1, %2, %3, %4};"
                         :: "r"(sb[s1] + my_off),
                            "r"(__float_as_uint(o.x)), "r"(__float_as_uint(o.y)),
                            "r"(__float_as_uint(o.z)), "r"(__float_as_uint(o.w))
                         : "memory");

            // Order generic-proxy STS before async-proxy bulk reads.
            asm volatile("fence.proxy.async.shared::cta;" ::: "memory");
            __syncthreads();

            // One thread emits both 4KB bulk stores as ONE group (8KB).
            if (tid == 0) {
                asm volatile(
                    "cp.async.bulk.global.shared::cta.bulk_group [%0], [%1], %2;"
                    :: "l"(obase + (size_t)d0 * plane), "r"(sb[s0]),
                       "r"((uint32_t)TILE_BYTES)
                    : "memory");
                asm volatile(
                    "cp.async.bulk.global.shared::cta.bulk_group [%0], [%1], %2;"
                    :: "l"(obase + (size_t)(d0 + 1) * plane), "r"(sb[s1]),
                       "r"((uint32_t)TILE_BYTES)
                    : "memory");
                asm volatile("cp.async.bulk.commit_group;" ::: "memory");
            }
        }
    }

    // Drain all pending bulk stores before CTA exit.
    if (tid == 0)
        asm volatile("cp.async.bulk.wait_group %0;" :: "n"(0) : "memory");
}

extern "C" void kernel_launch(void* const* d_in, const int* in_sizes, int n_in,
                              void* d_out, int out_size)
{
    const float* left  = (const float*)d_in[0];
    const float* right = (const float*)d_in[1];
    float* out = (float*)d_out;

    cost_generator_kernel<<<GRID, THREADS>>>(left, right, out);
}

// round 17
// speedup vs baseline: 1.1976x; 1.0063x over previous
#include <cuda_runtime.h>
#include <cuda_bf16.h>
#include <cstdint>

// CostGenerator: cost[b,c,d,h,w] = (w>=d) ? left[b,c,h,w] - right[b,c,h,w-d] : 0
// B=2, C=32, H=128, W=256, D=48 (f32). 403 MB out, 16 MB in.
//
// R15 vs R13 (66.0us wall / 62.8 ncu best): single-barrier software pipeline.
// R13 had 2 syncthreads per pair with the blocking wait_group BETWEEN them
// (all threads convoy behind tid0's wait). R15: ONE barrier per pair; tid0
// commits pair k-1 and reclaims AFTER the barrier while other warps already
// compute/STS pair k. Reuse distance 3 -> NSTAGE=6 tiles (29.4KB smem,
// occupancy 7). Safety: tiles(k)=tiles(k-3); iter k-1's wait (<=1 pending
// after committing group k-2) proves group k-3 read; published to all
// threads by iter k's barrier before any STS(k). Barriers 48 -> 24.
// Compute path identical to R13.

#define B_  2
#define C_  32
#define H_  128
#define W_  256
#define D_  48
#define PAD 48
#define ROWS_PER_BLOCK 4
#define THREADS 256
#define GRID (B_ * C_ * (H_ / ROWS_PER_BLOCK))   // 2048 CTAs
#define NSTAGE 6                                  // 3 pairs resident
#define NPAIRS (D_ / 2)                           // 24
#define TILE_BYTES (ROWS_PER_BLOCK * W_ * 4)      // 4096 B per d

__device__ __forceinline__ uint32_t smem_u32(const void* p) {
    uint32_t a;
    asm("{ .reg .u64 t; cvta.to.shared.u64 t, %1; cvt.u32.u64 %0, t; }"
        : "=r"(a) : "l"(p));
    return a;
}

__global__ __launch_bounds__(THREADS, 7)
void cost_generator_kernel(const float* __restrict__ left,
                           const float* __restrict__ right,
                           float* __restrict__ out)
{
    __shared__ float s_right[ROWS_PER_BLOCK][PAD + W_];
    __shared__ __align__(16) float s_out[NSTAGE][ROWS_PER_BLOCK * W_]; // 6x4KB

    const int tid = threadIdx.x;
    const int r   = tid >> 6;        // row within block: 0..3
    const int v   = tid & 63;        // float4 lane within row: 0..63
    const int w0  = v << 2;          // first w this thread owns (4-aligned)

    const int hb  = blockIdx.x % (H_ / ROWS_PER_BLOCK);
    const int bc  = blockIdx.x / (H_ / ROWS_PER_BLOCK);   // fused (b*C + c)
    const int h   = hb * ROWS_PER_BLOCK + r;

    const size_t in_off = ((size_t)bc * H_ + h) * W_;

    // Left values live in registers for the whole d-loop.
    const float4 l4 = *reinterpret_cast<const float4*>(left + in_off + w0);

    // Zero the pad and stage this row of right into smem (48x reuse).
    if (v < PAD / 4) {
        *reinterpret_cast<float4*>(&s_right[r][v << 2]) = make_float4(0.f, 0.f, 0.f, 0.f);
    }
    *reinterpret_cast<float4*>(&s_right[r][PAD + w0]) =
        *reinterpret_cast<const float4*>(right + in_off + w0);
    __syncthreads();

    const float* sr = &s_right[r][PAD];

    // Destination: per d, rows h0..h0+3 of plane (bc,d) = contiguous 4KB.
    const size_t plane = (size_t)H_ * W_;
    float* obase = out + ((size_t)bc * D_) * plane
                       + (size_t)(hb * ROWS_PER_BLOCK) * W_;

    uint32_t sb[NSTAGE];
    #pragma unroll
    for (int s = 0; s < NSTAGE; ++s) sb[s] = smem_u32(&s_out[s][0]);
    const uint32_t my_off = (uint32_t)tid * 16u;   // thread's 16B slot

    float4 Vhi, Vlo;

    #pragma unroll
    for (int k = 0; k < NPAIRS; ++k) {
        // ---- one barrier per pair ----
        if (k > 0) {
            __syncthreads();   // publishes STS(k-1); publishes iter k-1's
                               // reclaim guarantee (group k-3 read)
            if (tid == 0) {
                // Order all threads' STS(k-1) (acquired via the barrier)
                // before the async-proxy bulk reads.
                asm volatile("fence.proxy.async.shared::cta;" ::: "memory");
                const int dp = 2 * (k - 1);
                const int ta = 2 * ((k - 1) % 3);
                asm volatile(
                    "cp.async.bulk.global.shared::cta.bulk_group [%0], [%1], %2;"
                    :: "l"(obase + (size_t)dp * plane), "r"(sb[ta]),
                       "r"((uint32_t)TILE_BYTES) : "memory");
                asm volatile(
                    "cp.async.bulk.global.shared::cta.bulk_group [%0], [%1], %2;"
                    :: "l"(obase + (size_t)(dp + 1) * plane), "r"(sb[ta + 1]),
                       "r"((uint32_t)TILE_BYTES) : "memory");
                asm volatile("cp.async.bulk.commit_group;" ::: "memory");
                // Reclaim: <=1 pending leaves only group(k-1); group(k-2)
                // and older fully read. Result consumed at NEXT barrier.
                asm volatile("cp.async.bulk.wait_group.read %0;"
                             :: "n"(1) : "memory");
            }
        }

        // ---- compute pair k while tid0 handles the async bookkeeping ----
        const int g = k >> 1;
        const int p = k & 1;
        const int i0 = w0 - 4 * g;

        if (p == 0) {   // new window group: two aligned vector loads
            Vhi = *reinterpret_cast<const float4*>(sr + i0);
            Vlo = *reinterpret_cast<const float4*>(sr + i0 - 4);
        }

        const int ta = 2 * (k % 3);        // this pair's tiles

        float4 o;
        // first d of pair: j = 2p
        if (p == 0) {   // j=0 : {Vhi.x, Vhi.y, Vhi.z, Vhi.w}
            o.x = (i0     >= 0) ? (l4.x - Vhi.x) : 0.f;
            o.y = (i0 + 1 >= 0) ? (l4.y - Vhi.y) : 0.f;
            o.z = (i0 + 2 >= 0) ? (l4.z - Vhi.z) : 0.f;
            o.w = (i0 + 3 >= 0) ? (l4.w - Vhi.w) : 0.f;
        } else {        // j=2 : {Vlo.z, Vlo.w, Vhi.x, Vhi.y}
            o.x = (i0     >= 2) ? (l4.x - Vlo.z) : 0.f;
            o.y = (i0 + 1 >= 2) ? (l4.y - Vlo.w) : 0.f;
            o.z = (i0 + 2 >= 2) ? (l4.z - Vhi.x) : 0.f;
            o.w = (i0 + 3 >= 2) ? (l4.w - Vhi.y) : 0.f;
        }
        asm volatile("st.shared.v4.b32 [%0], {%1, %2, %3, %4};"
                     :: "r"(sb[ta] + my_off),
                        "r"(__float_as_uint(o.x)), "r"(__float_as_uint(o.y)),
                        "r"(__float_as_uint(o.z)), "r"(__float_as_uint(o.w))
                     : "memory");

        // second d of pair: j = 2p+1
        if (p == 0) {   // j=1 : {Vlo.w, Vhi.x, Vhi.y, Vhi.z}
            o.x = (i0     >= 1) ? (l4.x - Vlo.w) : 0.f;
            o.y = (i0 + 1 >= 1) ? (l4.y - Vhi.x) : 0.f;
            o.z = (i0 + 2 >= 1) ? (l4.z - Vhi.y) : 0.f;
            o.w = (i0 + 3 >= 1) ? (l4.w - Vhi.z) : 0.f;
        } else {        // j=3 : {Vlo.y, Vlo.z, Vlo.w, Vhi.x}
            o.x = (i0     >= 3) ? (l4.x - Vlo.y) : 0.f;
            o.y = (i0 + 1 >= 3) ? (l4.y - Vlo.z) : 0.f;
            o.z = (i0 + 2 >= 3) ? (l4.z - Vlo.w) : 0.f;
            o.w = (i0 + 3 >= 3) ? (l4.w - Vhi.x) : 0.f;
        }
        asm volatile("st.shared.v4.b32 [%0], {%1, %2, %3, %4};"
                     :: "r"(sb[ta + 1] + my_off),
                        "r"(__float_as_uint(o.x)), "r"(__float_as_uint(o.y)),
                        "r"(__float_as_uint(o.z)), "r"(__float_as_uint(o.w))
                     : "memory");
    }

    // ---- epilogue: flush final pair ----
    __syncthreads();
    if (tid == 0) {
        asm volatile("fence.proxy.async.shared::cta;" ::: "memory");
        const int dp = 2 * (NPAIRS - 1);
        const int ta = 2 * ((NPAIRS - 1) % 3);
        asm volatile(
            "cp.async.bulk.global.shared::cta.bulk_group [%0], [%1], %2;"
            :: "l"(obase + (size_t)dp * plane), "r"(sb[ta]),
               "r"((uint32_t)TILE_BYTES) : "memory");
        asm volatile(
            "cp.async.bulk.global.shared::cta.bulk_group [%0], [%1], %2;"
            :: "l"(obase + (size_t)(dp + 1) * plane), "r"(sb[ta + 1]),
               "r"((uint32_t)TILE_BYTES) : "memory");
        asm volatile("cp.async.bulk.commit_group;" ::: "memory");
        asm volatile("cp.async.bulk.wait_group %0;" :: "n"(0) : "memory");
    }
}

extern "C" void kernel_launch(void* const* d_in, const int* in_sizes, int n_in,
                              void* d_out, int out_size)
{
    const float* left  = (const float*)d_in[0];
    const float* right = (const float*)d_in[1];
    float* out = (float*)d_out;

    cost_generator_kernel<<<GRID, THREADS>>>(left, right, out);
}